// round 12
// baseline (speedup 1.0000x reference)
#include <cuda_runtime.h>
#include <math.h>

#define BSZ 1024
#define ISZ 2048
#define OSZ 1024
#define NW  32        // B/32 batch bit-words
#define SEQ 32
#define RSTRIDE 3072  // record slots per bg (mean ~2120, max ~2250)

// ---------------- device state (all re-initialized every launch) -------------
__device__ float    g_wT[ISZ*OSZ];     // weight, [I][O] layout (transposed)
__device__ float    g_A [ISZ*OSZ];     // running A = sum d^{t-k} M_k, [I][O]
__device__ unsigned g_sb[NW*ISZ];      // input spike bits, [bg][i]
__device__ unsigned g_zb[NW*OSZ];      // output spike bits, [bg][o]
__device__ float    g_S [ISZ];         // per-input batch spike counts
__device__ float    g_vf[BSZ*OSZ];     // fallback v if out_size too small
__device__ unsigned long long g_rec[NW*RSTRIDE];  // packed scatter records
__device__ unsigned g_rn[NW];          // padded record count per bg

// ---------------- K0a: build input bitmasks + column counts ------------------
__global__ void k_build_s(const float* __restrict__ s) {
    int id = blockIdx.x * blockDim.x + threadIdx.x;
    if (id >= NW * ISZ) return;
    int i  = id & (ISZ - 1);
    int bg = id >> 11;
    unsigned w = 0u;
#pragma unroll
    for (int k = 0; k < 32; k++) {
        float x = s[(bg * 32 + k) * ISZ + i];
        w |= (x != 0.0f ? 1u : 0u) << k;
    }
    g_sb[bg * ISZ + i] = w;
    atomicAdd(&g_S[i], (float)__popc(w));   // exact integer adds: order-independent
}

// ---------------- K0c: build branch-free scatter records ---------------------
// Record u64: low32 = i*4096 (byte offset into a wT row-block), high32 =
// acc_off0 | acc_off1<<16, acc_off = b*128 bytes (row stride 32 floats),
// trash row = 32 (offset 4096). Up to 2 set bits per record; odd popcounts pad
// slot 2 with trash. List padded to a multiple of 64 with pure-trash records
// so the 8 k_fwd slices divide evenly (and by 8 for the unrolled loop).
__global__ __launch_bounds__(256) void k_build_rec() {
    __shared__ unsigned scan[256];
    int bg = blockIdx.x, t = threadIdx.x;
    unsigned m[8];
    unsigned nr = 0;
#pragma unroll
    for (int k = 0; k < 8; k++) {
        m[k] = g_sb[bg * ISZ + t * 8 + k];
        nr += (__popc(m[k]) + 1) >> 1;
    }
    scan[t] = nr;
    __syncthreads();
    for (int off = 1; off < 256; off <<= 1) {          // inclusive Hillis-Steele
        unsigned v = (t >= off) ? scan[t - off] : 0u;
        __syncthreads();
        scan[t] += v;
        __syncthreads();
    }
    unsigned idx = scan[t] - nr;
    unsigned long long* out = g_rec + (size_t)bg * RSTRIDE;
#pragma unroll
    for (int k = 0; k < 8; k++) {
        unsigned mm = m[k];
        unsigned long long wo = ((unsigned long long)(t * 8 + k)) << 12;
        while (mm) {
            unsigned a0 = (unsigned)(__ffs(mm) - 1) * 128u;
            mm &= mm - 1;
            unsigned a1 = 4096u;                       // trash
            if (mm) { a1 = (unsigned)(__ffs(mm) - 1) * 128u; mm &= mm - 1; }
            out[idx++] = wo | (((unsigned long long)(a0 | (a1 << 16))) << 32);
        }
    }
    __syncthreads();
    unsigned tot = scan[255];
    unsigned pad = (tot + 63u) & ~63u;
    const unsigned long long trash_rec =
        ((unsigned long long)(4096u | (4096u << 16))) << 32;
    for (unsigned j = tot + t; j < pad; j += 256) out[j] = trash_rec;
    if (t == 0) g_rn[bg] = pad;
}

// ---------------- K0b: tiled transpose weight [O][I] -> wT [I][O] ------------
__global__ __launch_bounds__(256) void k_wT(const float* __restrict__ w) {
    __shared__ float tile[32][33];
    int tx = threadIdx.x, ty = threadIdx.y;           // block (32, 8)
    int x = blockIdx.x * 32 + tx;                     // i
    int y = blockIdx.y * 32 + ty;                     // o
#pragma unroll
    for (int j = 0; j < 32; j += 8)
        tile[ty + j][tx] = w[(size_t)(y + j) * ISZ + x];
    __syncthreads();
    int xo = blockIdx.y * 32 + tx;
    int yi = blockIdx.x * 32 + ty;
#pragma unroll
    for (int j = 0; j < 32; j += 8)
        g_wT[(size_t)(yi + j) * OSZ + xo] = tile[tx][ty + j];
}

// ---------------- K1: record-driven sparse forward + LIF ---------------------
// grid (O/32, NW) = 1024 CTAs, block (32, 8). CTA: 32 outputs x one bg.
// 8 slices of the record list, private 33-row acc slabs (row 32 = trash).
// 34KB smem -> 6 CTAs/SM resident, 48 warps/SM; straight-line inner loop.
__global__ __launch_bounds__(256) void k_fwd(const float* __restrict__ bias,
                                             float* __restrict__ v,
                                             float* __restrict__ zout,
                                             float vdecay, int last) {
    __shared__ float    acc[8 * 33 * 32];
    __shared__ unsigned zsh[32];

    int tid = threadIdx.x;            // 0..31  (output lane)
    int ch  = threadIdx.y;            // 0..7   (record slice)
    int bg  = blockIdx.y;
    int o   = blockIdx.x * 32 + tid;

    for (int j = tid; j < 33 * 32; j += 32) acc[ch * (33 * 32) + j] = 0.0f;
    if (ch == 0) zsh[tid] = 0u;
    __syncthreads();

    unsigned per = g_rn[bg] >> 3;                     // multiple of 8
    const unsigned long long* rec = g_rec + (size_t)bg * RSTRIDE + ch * per;
    char* accbase = (char*)(acc + ch * (33 * 32)) + tid * 4;
    const char* wcb = (const char*)g_wT + (size_t)o * 4;

#pragma unroll 4
    for (unsigned r = 0; r < per; r += 2) {
        uint4 q = __ldg((const uint4*)&rec[r]);       // 2 records
        float w0 = __ldg((const float*)(wcb + q.x));
        float w1 = __ldg((const float*)(wcb + q.z));
        float* a00 = (float*)(accbase + (q.y & 0xFFFFu));
        float* a01 = (float*)(accbase + (q.y >> 16));
        float* a10 = (float*)(accbase + (q.w & 0xFFFFu));
        float* a11 = (float*)(accbase + (q.w >> 16));
        *a00 += w0;
        *a01 += w0;
        *a10 += w1;
        *a11 += w1;
    }
    __syncthreads();

    float bi = bias[o];
#pragma unroll
    for (int bb = 0; bb < 4; bb++) {
        int b = (ch << 2) | bb;
        // slice-order sequential reduce (deterministic, ascending record order)
        float sum = acc[0 * (33 * 32) + b * 32 + tid];
#pragma unroll
        for (int sl = 1; sl < 8; sl++) sum += acc[sl * (33 * 32) + b * 32 + tid];
        int idx = (bg * 32 + b) * OSZ + o;
        float vv = v[idx] * vdecay + sum + bi;
        bool sp = (vv >= 1.0f);
        if (last) zout[idx] = sp ? 1.0f : 0.0f;
        v[idx] = sp ? 0.0f : vv;          // v*(1-z) exactly
        if (sp) atomicOr(&zsh[tid], 1u << b);   // OR: order-independent
    }
    __syncthreads();
    if (ch == 0) g_zb[bg * OSZ + blockIdx.x * 32 + tid] = zsh[tid];
}

// ---------------- K2: M = z^T s popcount + A + w update, 4x4 register tile ---
// grid (O/64, I/32), block 128. Thread owns a 4o x 4il cell block.
__global__ __launch_bounds__(128) void k_upd(float a_t, float b_t, float c_t,
                                             float dpost, float etap, float etam) {
    __shared__ unsigned zt[NW * 64];   // [w][o-lane]   8KB
    __shared__ unsigned st[NW * 32];   // [w][il]       4KB
    __shared__ float    Ssh[32];
    int tid = threadIdx.x;
    int o0  = blockIdx.x * 64;
    int i0  = blockIdx.y * 32;

    for (int j = tid; j < NW * 64; j += 128) {
        int w = j >> 6, oo = j & 63;
        zt[j] = g_zb[w * OSZ + o0 + oo];
    }
    for (int j = tid; j < NW * 32; j += 128) {
        int w = j >> 5, il = j & 31;
        st[j] = g_sb[w * ISZ + i0 + il];
    }
    if (tid < 32) Ssh[tid] = g_S[i0 + tid];
    __syncthreads();

    int oq = (tid & 15) << 2;          // o-quad 0..60
    int iq = (tid >> 4) << 2;          // il-quad 0..28

    int cnt[16];
#pragma unroll
    for (int k = 0; k < 16; k++) cnt[k] = 0;
    int zc0 = 0, zc1 = 0, zc2 = 0, zc3 = 0;

#pragma unroll 8
    for (int w = 0; w < NW; w++) {
        uint4 z4 = *(const uint4*)&zt[w * 64 + oq];
        uint4 s4 = *(const uint4*)&st[w * 32 + iq];
        zc0 += __popc(z4.x); zc1 += __popc(z4.y);
        zc2 += __popc(z4.z); zc3 += __popc(z4.w);
        cnt[ 0] += __popc(s4.x & z4.x); cnt[ 1] += __popc(s4.x & z4.y);
        cnt[ 2] += __popc(s4.x & z4.z); cnt[ 3] += __popc(s4.x & z4.w);
        cnt[ 4] += __popc(s4.y & z4.x); cnt[ 5] += __popc(s4.y & z4.y);
        cnt[ 6] += __popc(s4.y & z4.z); cnt[ 7] += __popc(s4.y & z4.w);
        cnt[ 8] += __popc(s4.z & z4.x); cnt[ 9] += __popc(s4.z & z4.y);
        cnt[10] += __popc(s4.z & z4.z); cnt[11] += __popc(s4.z & z4.w);
        cnt[12] += __popc(s4.w & z4.x); cnt[13] += __popc(s4.w & z4.y);
        cnt[14] += __popc(s4.w & z4.z); cnt[15] += __popc(s4.w & z4.w);
    }
    float Zf0 = (float)zc0, Zf1 = (float)zc1, Zf2 = (float)zc2, Zf3 = (float)zc3;

#pragma unroll
    for (int c = 0; c < 4; c++) {
        int il  = iq + c;
        int idx = (i0 + il) * OSZ + o0 + oq;
        float Sv = Ssh[il];
        float4 Av = *(const float4*)&g_A[idx];
        float m0 = (float)cnt[c * 4 + 0], m1 = (float)cnt[c * 4 + 1];
        float m2 = (float)cnt[c * 4 + 2], m3 = (float)cnt[c * 4 + 3];
        float4 An;
        An.x = Av.x * dpost + m0;  An.y = Av.y * dpost + m1;
        An.z = Av.z * dpost + m2;  An.w = Av.w * dpost + m3;
        *(float4*)&g_A[idx] = An;
        float4 Wv = *(const float4*)&g_wT[idx];
        float cs = c_t * Sv;
        Wv.x += etap * (a_t * Zf0 + b_t * m0) - etam * (cs + An.x);
        Wv.y += etap * (a_t * Zf1 + b_t * m1) - etam * (cs + An.y);
        Wv.z += etap * (a_t * Zf2 + b_t * m2) - etam * (cs + An.z);
        Wv.w += etap * (a_t * Zf3 + b_t * m3) - etam * (cs + An.w);
        Wv.x = fminf(fmaxf(Wv.x, -1.0f), 1.0f);
        Wv.y = fminf(fmaxf(Wv.y, -1.0f), 1.0f);
        Wv.z = fminf(fmaxf(Wv.z, -1.0f), 1.0f);
        Wv.w = fminf(fmaxf(Wv.w, -1.0f), 1.0f);
        *(float4*)&g_wT[idx] = Wv;
    }
}

// ---------------- K3: tiled transpose wT [I][O] -> output [O][I] -------------
__global__ __launch_bounds__(256) void k_wout(float* __restrict__ out) {
    __shared__ float tile[32][33];
    int tx = threadIdx.x, ty = threadIdx.y;           // block (32, 8)
    int x = blockIdx.x * 32 + tx;                     // o
    int y = blockIdx.y * 32 + ty;                     // i
#pragma unroll
    for (int j = 0; j < 32; j += 8)
        tile[ty + j][tx] = g_wT[(size_t)(y + j) * OSZ + x];
    __syncthreads();
    int xi = blockIdx.y * 32 + tx;
    int yo = blockIdx.x * 32 + ty;
#pragma unroll
    for (int j = 0; j < 32; j += 8)
        out[(size_t)(yo + j) * ISZ + xi] = tile[tx][ty + j];
}

// -----------------------------------------------------------------------------
extern "C" void kernel_launch(void* const* d_in, const int* in_sizes, int n_in,
                              void* d_out, int out_size) {
    const float* s    = (const float*)d_in[0];   // input_spikes [B,I]
    const float* w    = (const float*)d_in[1];   // weight [O,I]
    const float* bias = (const float*)d_in[2];   // bias [O]
    float* out  = (float*)d_out;
    float* zout = out;

    void *pA = nullptr, *pS = nullptr, *pV = nullptr;
    cudaGetSymbolAddress(&pA, g_A);
    cudaGetSymbolAddress(&pS, g_S);
    cudaGetSymbolAddress(&pV, g_vf);

    float* v = (out_size >= 2 * BSZ * OSZ) ? (out + BSZ * OSZ) : (float*)pV;

    // per-launch state init (graph-replayed every run -> deterministic)
    cudaMemsetAsync(pA, 0, (size_t)ISZ * OSZ * sizeof(float));
    cudaMemsetAsync(pS, 0, (size_t)ISZ * sizeof(float));
    cudaMemsetAsync(v,  0, (size_t)BSZ * OSZ * sizeof(float));

    k_build_s<<<(NW * ISZ) / 256, 256>>>(s);
    k_build_rec<<<NW, 256>>>();
    k_wT<<<dim3(ISZ / 32, OSZ / 32), dim3(32, 8)>>>(w);

    // fp32-iterated trace constants, matching the reference's iterative decay
    const float d = (float)exp(-0.05);   // decay_pre = decay_post = v_decay
    float p0 = 1.0f, p1 = 1.0f;
    for (int t = 0; t < SEQ; t++) {
        p0 = p0 * d;                 // tpre/tpost trajectory for s=0 (= d^t, fp32)
        p1 = p1 * d + 1.0f;          // tpre trajectory for s=1
        k_fwd<<<dim3(OSZ / 32, NW), dim3(32, 8)>>>(bias, v, zout, d, t == SEQ - 1);
        k_upd<<<dim3(OSZ / 64, ISZ / 32), 128>>>(p0, p1 - p0, p0, d, 1e-3f, 1e-3f);
    }

    if (out_size >= 2 * BSZ * OSZ + ISZ * OSZ)
        k_wout<<<dim3(OSZ / 32, ISZ / 32), dim3(32, 8)>>>(out + 2 * BSZ * OSZ);
}

// round 13
// speedup vs baseline: 1.7381x; 1.7381x over previous
#include <cuda_runtime.h>
#include <math.h>

#define BSZ 1024
#define ISZ 2048
#define OSZ 1024
#define NW  32        // B/32 batch bit-words
#define SEQ 32
#define CSTRIDE 256   // CSR slots per batch (mean nnz ~102, +15 sigma < 256)

// ---------------- device state (all re-initialized every launch) -------------
__device__ float    g_wT[(ISZ+1)*OSZ]; // weight [I][O] (+ zero row at i=ISZ)
__device__ float    g_A [ISZ*OSZ];     // running A = sum d^{t-k} M_k, [I][O]
__device__ unsigned g_sb[NW*ISZ];      // input spike bits, [bg][i]
__device__ unsigned g_zb[NW*OSZ];      // output spike bits, [bg][o]
__device__ float    g_S [ISZ];         // per-input batch spike counts
__device__ float    g_vf[BSZ*OSZ];     // fallback v if out_size too small
__device__ unsigned short g_csr[BSZ*CSTRIDE];  // per-batch spiking-i lists
__device__ unsigned g_ns[BSZ];         // padded (x8) list length per batch

// ---------------- K0a: build input bitmasks + column counts ------------------
__global__ void k_build_s(const float* __restrict__ s) {
    int id = blockIdx.x * blockDim.x + threadIdx.x;
    if (id >= NW * ISZ) return;
    int i  = id & (ISZ - 1);
    int bg = id >> 11;
    unsigned w = 0u;
#pragma unroll
    for (int k = 0; k < 32; k++) {
        float x = s[(bg * 32 + k) * ISZ + i];
        w |= (x != 0.0f ? 1u : 0u) << k;
    }
    g_sb[bg * ISZ + i] = w;
    atomicAdd(&g_S[i], (float)__popc(w));   // exact integer adds: order-independent
}

// ---------------- K0c: build per-batch CSR spike lists (ballot scan) ---------
// One warp per batch; ascending i order; padded to a multiple of 8 with i=ISZ
// (a zero weight row), so the gather loop is branch-free.
__global__ __launch_bounds__(256) void k_build_csr(const float* __restrict__ s) {
    int b    = (blockIdx.x * 256 + threadIdx.x) >> 5;   // batch 0..1023
    int lane = threadIdx.x & 31;
    const float* row = s + (size_t)b * ISZ;
    unsigned short* out = g_csr + b * CSTRIDE;
    unsigned base = 0;
    for (int c = 0; c < ISZ / 32; c++) {
        float x = row[c * 32 + lane];
        unsigned m = __ballot_sync(0xFFFFFFFFu, x != 0.0f);
        if (m & (1u << lane)) {
            int pos = base + __popc(m & ((1u << lane) - 1u));
            out[pos] = (unsigned short)(c * 32 + lane);
        }
        base += __popc(m);
    }
    unsigned padded = (base + 7u) & ~7u;
    for (unsigned j = base + lane; j < padded; j += 32)
        out[j] = (unsigned short)ISZ;                   // zero-row pad
    if (lane == 0) g_ns[b] = padded;
}

// ---------------- K0b: tiled transpose weight [O][I] -> wT [I][O] ------------
__global__ __launch_bounds__(256) void k_wT(const float* __restrict__ w) {
    __shared__ float tile[32][33];
    int tx = threadIdx.x, ty = threadIdx.y;           // block (32, 8)
    int x = blockIdx.x * 32 + tx;                     // i
    int y = blockIdx.y * 32 + ty;                     // o
#pragma unroll
    for (int j = 0; j < 32; j += 8)
        tile[ty + j][tx] = w[(size_t)(y + j) * ISZ + x];
    __syncthreads();
    int xo = blockIdx.y * 32 + tx;
    int yi = blockIdx.x * 32 + ty;
#pragma unroll
    for (int j = 0; j < 32; j += 8)
        g_wT[(size_t)(yi + j) * OSZ + xo] = tile[tx][ty + j];
}

// ---------------- K1: CSR-gather forward + LIF + spike-bit build -------------
// grid (O/32, B/32), block (32, 32). Warp = one batch; lanes = 32 outputs.
// Register accumulation (4 fixed-order partials), no smem RMW, no atomics.
// Per 8 spikes: 1 LDS.128 of packed u16 indices + 8 coalesced LDG + 8 FADD.
__global__ __launch_bounds__(1024) void k_fwd(const float* __restrict__ bias,
                                              float* __restrict__ v,
                                              float* __restrict__ zout,
                                              float vdecay, int last) {
    __shared__ unsigned short sidx[32 * CSTRIDE];     // 16KB
    __shared__ unsigned char  spk[32][32];            // 1KB pred matrix [b][o]
    int lane = threadIdx.x;
    int wy   = threadIdx.y;                           // batch-in-group
    int b    = blockIdx.y * 32 + wy;
    int o    = blockIdx.x * 32 + lane;

    unsigned n = g_ns[b];
    {
        const unsigned short* src = g_csr + b * CSTRIDE;
        for (int k = lane; k < CSTRIDE; k += 32) sidx[wy * CSTRIDE + k] = src[k];
    }
    __syncwarp();                                     // per-warp private list

    const float* wrow = g_wT + o;
    float a0 = 0.0f, a1 = 0.0f, a2 = 0.0f, a3 = 0.0f;
    const uint4* q4 = (const uint4*)(sidx + wy * CSTRIDE);
    unsigned n8 = n >> 3;
    for (unsigned k = 0; k < n8; k++) {
        uint4 q = q4[k];                              // 8 packed u16 indices
        unsigned i0 = q.x & 0xFFFFu, i1 = q.x >> 16;
        unsigned i2 = q.y & 0xFFFFu, i3 = q.y >> 16;
        unsigned i4 = q.z & 0xFFFFu, i5 = q.z >> 16;
        unsigned i6 = q.w & 0xFFFFu, i7 = q.w >> 16;
        a0 += wrow[i0 * OSZ];
        a1 += wrow[i1 * OSZ];
        a2 += wrow[i2 * OSZ];
        a3 += wrow[i3 * OSZ];
        a0 += wrow[i4 * OSZ];
        a1 += wrow[i5 * OSZ];
        a2 += wrow[i6 * OSZ];
        a3 += wrow[i7 * OSZ];
    }
    float sum = (a0 + a1) + (a2 + a3);                // fixed, deterministic

    int idxv = b * OSZ + o;
    float vv = v[idxv] * vdecay + sum + bias[o];
    bool sp = (vv >= 1.0f);
    if (last) zout[idxv] = sp ? 1.0f : 0.0f;
    v[idxv] = sp ? 0.0f : vv;                         // v*(1-z) exactly
    spk[wy][lane] = (unsigned char)sp;
    __syncthreads();

    if (wy == 0) {                                    // bit-transpose 32x32
        unsigned wd = 0u;
#pragma unroll
        for (int k = 0; k < 32; k++)
            wd |= ((unsigned)spk[k][lane]) << k;
        g_zb[blockIdx.y * OSZ + o] = wd;
    }
}

// ---------------- K2: M = z^T s popcount + A + w update, 4x4 register tile ---
// grid (O/64, I/32), block 128. Thread owns a 4o x 4il cell block.
__global__ __launch_bounds__(128) void k_upd(float a_t, float b_t, float c_t,
                                             float dpost, float etap, float etam) {
    __shared__ unsigned zt[NW * 64];   // [w][o-lane]   8KB
    __shared__ unsigned st[NW * 32];   // [w][il]       4KB
    __shared__ float    Ssh[32];
    int tid = threadIdx.x;
    int o0  = blockIdx.x * 64;
    int i0  = blockIdx.y * 32;

    for (int j = tid; j < NW * 64; j += 128) {
        int w = j >> 6, oo = j & 63;
        zt[j] = g_zb[w * OSZ + o0 + oo];
    }
    for (int j = tid; j < NW * 32; j += 128) {
        int w = j >> 5, il = j & 31;
        st[j] = g_sb[w * ISZ + i0 + il];
    }
    if (tid < 32) Ssh[tid] = g_S[i0 + tid];
    __syncthreads();

    int oq = (tid & 15) << 2;          // o-quad 0..60
    int iq = (tid >> 4) << 2;          // il-quad 0..28

    int cnt[16];
#pragma unroll
    for (int k = 0; k < 16; k++) cnt[k] = 0;
    int zc0 = 0, zc1 = 0, zc2 = 0, zc3 = 0;

#pragma unroll 8
    for (int w = 0; w < NW; w++) {
        uint4 z4 = *(const uint4*)&zt[w * 64 + oq];
        uint4 s4 = *(const uint4*)&st[w * 32 + iq];
        zc0 += __popc(z4.x); zc1 += __popc(z4.y);
        zc2 += __popc(z4.z); zc3 += __popc(z4.w);
        cnt[ 0] += __popc(s4.x & z4.x); cnt[ 1] += __popc(s4.x & z4.y);
        cnt[ 2] += __popc(s4.x & z4.z); cnt[ 3] += __popc(s4.x & z4.w);
        cnt[ 4] += __popc(s4.y & z4.x); cnt[ 5] += __popc(s4.y & z4.y);
        cnt[ 6] += __popc(s4.y & z4.z); cnt[ 7] += __popc(s4.y & z4.w);
        cnt[ 8] += __popc(s4.z & z4.x); cnt[ 9] += __popc(s4.z & z4.y);
        cnt[10] += __popc(s4.z & z4.z); cnt[11] += __popc(s4.z & z4.w);
        cnt[12] += __popc(s4.w & z4.x); cnt[13] += __popc(s4.w & z4.y);
        cnt[14] += __popc(s4.w & z4.z); cnt[15] += __popc(s4.w & z4.w);
    }
    float Zf0 = (float)zc0, Zf1 = (float)zc1, Zf2 = (float)zc2, Zf3 = (float)zc3;

#pragma unroll
    for (int c = 0; c < 4; c++) {
        int il  = iq + c;
        int idx = (i0 + il) * OSZ + o0 + oq;
        float Sv = Ssh[il];
        float4 Av = *(const float4*)&g_A[idx];
        float m0 = (float)cnt[c * 4 + 0], m1 = (float)cnt[c * 4 + 1];
        float m2 = (float)cnt[c * 4 + 2], m3 = (float)cnt[c * 4 + 3];
        float4 An;
        An.x = Av.x * dpost + m0;  An.y = Av.y * dpost + m1;
        An.z = Av.z * dpost + m2;  An.w = Av.w * dpost + m3;
        *(float4*)&g_A[idx] = An;
        float4 Wv = *(const float4*)&g_wT[idx];
        float cs = c_t * Sv;
        Wv.x += etap * (a_t * Zf0 + b_t * m0) - etam * (cs + An.x);
        Wv.y += etap * (a_t * Zf1 + b_t * m1) - etam * (cs + An.y);
        Wv.z += etap * (a_t * Zf2 + b_t * m2) - etam * (cs + An.z);
        Wv.w += etap * (a_t * Zf3 + b_t * m3) - etam * (cs + An.w);
        Wv.x = fminf(fmaxf(Wv.x, -1.0f), 1.0f);
        Wv.y = fminf(fmaxf(Wv.y, -1.0f), 1.0f);
        Wv.z = fminf(fmaxf(Wv.z, -1.0f), 1.0f);
        Wv.w = fminf(fmaxf(Wv.w, -1.0f), 1.0f);
        *(float4*)&g_wT[idx] = Wv;
    }
}

// ---------------- K3: tiled transpose wT [I][O] -> output [O][I] -------------
__global__ __launch_bounds__(256) void k_wout(float* __restrict__ out) {
    __shared__ float tile[32][33];
    int tx = threadIdx.x, ty = threadIdx.y;           // block (32, 8)
    int x = blockIdx.x * 32 + tx;                     // o
    int y = blockIdx.y * 32 + ty;                     // i
#pragma unroll
    for (int j = 0; j < 32; j += 8)
        tile[ty + j][tx] = g_wT[(size_t)(y + j) * OSZ + x];
    __syncthreads();
    int xi = blockIdx.y * 32 + tx;
    int yo = blockIdx.x * 32 + ty;
#pragma unroll
    for (int j = 0; j < 32; j += 8)
        out[(size_t)(yo + j) * ISZ + xi] = tile[tx][ty + j];
}

// -----------------------------------------------------------------------------
extern "C" void kernel_launch(void* const* d_in, const int* in_sizes, int n_in,
                              void* d_out, int out_size) {
    const float* s    = (const float*)d_in[0];   // input_spikes [B,I]
    const float* w    = (const float*)d_in[1];   // weight [O,I]
    const float* bias = (const float*)d_in[2];   // bias [O]
    float* out  = (float*)d_out;
    float* zout = out;

    void *pA = nullptr, *pS = nullptr, *pV = nullptr, *pW = nullptr;
    cudaGetSymbolAddress(&pA, g_A);
    cudaGetSymbolAddress(&pS, g_S);
    cudaGetSymbolAddress(&pV, g_vf);
    cudaGetSymbolAddress(&pW, g_wT);

    float* v = (out_size >= 2 * BSZ * OSZ) ? (out + BSZ * OSZ) : (float*)pV;

    // per-launch state init (graph-replayed every run -> deterministic)
    cudaMemsetAsync(pA, 0, (size_t)ISZ * OSZ * sizeof(float));
    cudaMemsetAsync(pS, 0, (size_t)ISZ * sizeof(float));
    cudaMemsetAsync(v,  0, (size_t)BSZ * OSZ * sizeof(float));
    cudaMemsetAsync((char*)pW + (size_t)ISZ * OSZ * sizeof(float), 0,
                    OSZ * sizeof(float));        // zero pad row i=ISZ

    k_build_s<<<(NW * ISZ) / 256, 256>>>(s);
    k_build_csr<<<BSZ / 8, 256>>>(s);
    k_wT<<<dim3(ISZ / 32, OSZ / 32), dim3(32, 8)>>>(w);

    // fp32-iterated trace constants, matching the reference's iterative decay
    const float d = (float)exp(-0.05);   // decay_pre = decay_post = v_decay
    float p0 = 1.0f, p1 = 1.0f;
    for (int t = 0; t < SEQ; t++) {
        p0 = p0 * d;                 // tpre/tpost trajectory for s=0 (= d^t, fp32)
        p1 = p1 * d + 1.0f;          // tpre trajectory for s=1
        k_fwd<<<dim3(OSZ / 32, BSZ / 32), dim3(32, 32)>>>(bias, v, zout, d, t == SEQ - 1);
        k_upd<<<dim3(OSZ / 64, ISZ / 32), 128>>>(p0, p1 - p0, p0, d, 1e-3f, 1e-3f);
    }

    if (out_size >= 2 * BSZ * OSZ + ISZ * OSZ)
        k_wout<<<dim3(OSZ / 32, ISZ / 32), dim3(32, 8)>>>(out + 2 * BSZ * OSZ);
}